// round 1
// baseline (speedup 1.0000x reference)
#include <cuda_runtime.h>
#include <math_constants.h>

// ---------------------------------------------------------------------------
// Quanv 3x3 layer: 9-qubit statevector sim, one warp per simulation.
//
// State bit assignment (free choice; measurement is on qubit 0):
//   qubit 0 -> local bit 0 (mask 1)     qubit 1 -> lane bit 0 (mask 1)
//   qubit 2 -> local bit 1 (mask 2)     qubit 3 -> lane bit 1 (mask 2)
//   qubit 4 -> local bit 2 (mask 4)     qubit 5 -> lane bit 2 (mask 4)
//   qubit 6 -> local bit 3 (mask 8)     qubit 7 -> lane bit 3 (mask 8)
//                                       qubit 8 -> lane bit 4 (mask 16)
// Each lane holds 16 complex amplitudes (local index l = bits of q0,q2,q4,q6).
// Only the (ctrl=8, tgt=7) CRX requires a lane exchange (shfl_xor by 8).
// ---------------------------------------------------------------------------

#define NPIX (8 * 30 * 30)
#define NSIM (8 * 4 * 28 * 28)   // 25088

__device__ float2 g_pix[NPIX];     // (c, s) encoding coefficients per pixel
__device__ float4 g_theta[4 * 8];  // per (channel, gate-pair): czr, czs, cxr, cxs

// --------------------------- precompute ------------------------------------
__global__ void precompute_kernel(const float* __restrict__ x,
                                  const float* __restrict__ qp) {
    int tid = blockIdx.x * blockDim.x + threadIdx.x;
    if (tid < NPIX) {
        // x layout (8,30,30,3); avg over channels.
        const float* px = x + 3 * tid;
        float a = (px[0] + px[1] + px[2]) * (1.0f / 3.0f);
        // RX angle t = 2*pi*a - pi, half-angle h = pi*a - pi/2
        // c = cos(h) = sin(pi*a),  s = sin(h) = -cos(pi*a)
        float sp, cp;
        sincosf(CUDART_PI_F * a, &sp, &cp);
        g_pix[tid] = make_float2(sp, -cp);
    } else if (tid < NPIX + 32) {
        int e = tid - NPIX;          // e = ch*8 + k
        int ch = e >> 3, k = e & 7;
        float tz = qp[ch * 16 + 2 * k];
        float tx = qp[ch * 16 + 2 * k + 1];
        float szs, czr, sxs, cxr;
        sincosf(tz * 0.5f, &szs, &czr);
        sincosf(tx * 0.5f, &sxs, &cxr);
        g_theta[e] = make_float4(czr, szs, cxr, sxs);
    }
}

// ------------------------- gate helpers ------------------------------------
// CRZ: ctrl=1 amplitudes get phase (czr - i*czs) if tgt=0 else (czr + i*czs).
// CRX: ctrl=1 pairs over tgt bit mix with [[c,-is],[-is,c]].

// ctrl is a LANE bit (uniform across the 16 local amps), tgt is LOCAL.
template <int CB, int TM>
__device__ __forceinline__ void gate_laneC_localT(float (&ar)[16], float (&ai)[16],
                                                  const float4 tc, int lane) {
    if (lane & CB) {
        // CRZ
#pragma unroll
        for (int l = 0; l < 16; l++) {
            float ph = (l & TM) ? tc.y : -tc.y;
            float nr = ar[l] * tc.x - ai[l] * ph;
            float ni = ar[l] * ph + ai[l] * tc.x;
            ar[l] = nr; ai[l] = ni;
        }
        // CRX
#pragma unroll
        for (int l = 0; l < 16; l++) {
            if (!(l & TM)) {
                int m = l | TM;
                float n0r = tc.z * ar[l] + tc.w * ai[m];
                float n0i = tc.z * ai[l] - tc.w * ar[m];
                float n1r = tc.z * ar[m] + tc.w * ai[l];
                float n1i = tc.z * ai[m] - tc.w * ar[l];
                ar[l] = n0r; ai[l] = n0i; ar[m] = n1r; ai[m] = n1i;
            }
        }
    }
}

// ctrl and tgt are both LOCAL bits (fully compile-time predicates).
template <int CM, int TM>
__device__ __forceinline__ void gate_localC_localT(float (&ar)[16], float (&ai)[16],
                                                   const float4 tc) {
    // CRZ
#pragma unroll
    for (int l = 0; l < 16; l++) {
        if (l & CM) {
            float ph = (l & TM) ? tc.y : -tc.y;
            float nr = ar[l] * tc.x - ai[l] * ph;
            float ni = ar[l] * ph + ai[l] * tc.x;
            ar[l] = nr; ai[l] = ni;
        }
    }
    // CRX
#pragma unroll
    for (int l = 0; l < 16; l++) {
        if ((l & CM) && !(l & TM)) {
            int m = l | TM;
            float n0r = tc.z * ar[l] + tc.w * ai[m];
            float n0i = tc.z * ai[l] - tc.w * ar[m];
            float n1r = tc.z * ar[m] + tc.w * ai[l];
            float n1i = tc.z * ai[m] - tc.w * ar[l];
            ar[l] = n0r; ai[l] = n0i; ar[m] = n1r; ai[m] = n1i;
        }
    }
}

// ctrl = lane bit 4 (q8), tgt = lane bit 3 (q7): needs a lane exchange.
__device__ __forceinline__ void gate_q8_q7(float (&ar)[16], float (&ai)[16],
                                           const float4 tc, int lane) {
    // CRZ: phase uniform across all 16 local amps of a lane.
    if (lane & 16) {
        float ph = (lane & 8) ? tc.y : -tc.y;
#pragma unroll
        for (int l = 0; l < 16; l++) {
            float nr = ar[l] * tc.x - ai[l] * ph;
            float ni = ar[l] * ph + ai[l] * tc.x;
            ar[l] = nr; ai[l] = ni;
        }
    }
    // CRX over lane bit 3: new = (c*self_r + s*partner_i, c*self_i - s*partner_r)
    // for BOTH halves (symmetric). Shuffle executed by all lanes.
    bool act = (lane & 16) != 0;
#pragma unroll
    for (int l = 0; l < 16; l++) {
        float pr = __shfl_xor_sync(0xffffffffu, ar[l], 8);
        float pi = __shfl_xor_sync(0xffffffffu, ai[l], 8);
        if (act) {
            float nr = tc.z * ar[l] + tc.w * pi;
            float ni = tc.z * ai[l] - tc.w * pr;
            ar[l] = nr; ai[l] = ni;
        }
    }
}

// ----------------------------- main kernel ---------------------------------
__global__ void __launch_bounds__(256) quanv_kernel(float* __restrict__ out) {
    int wid = (blockIdx.x * blockDim.x + threadIdx.x) >> 5;
    int lane = threadIdx.x & 31;
    if (wid >= NSIM) return;

    int b   = wid / 3136;             // 4*28*28
    int r1  = wid - b * 3136;
    int ch  = r1 / 784;
    int pos = r1 - ch * 784;
    int i   = pos / 28;
    int j   = pos - i * 28;

    // Load the 9 encoding coefficient pairs (broadcast loads, L1/L2 hot).
    float c[9], s[9];
    const float2* pix = g_pix + b * 900 + i * 30 + j;
#pragma unroll
    for (int q = 0; q < 9; q++) {
        float2 v = pix[(q / 3) * 30 + (q % 3)];
        c[q] = v.x; s[q] = v.y;
    }

    // ---- Initialize product state after the RX encoding layer. ----
    float laneF = ((lane & 1)  ? s[1] : c[1])
                * ((lane & 2)  ? s[3] : c[3])
                * ((lane & 4)  ? s[5] : c[5])
                * ((lane & 8)  ? s[7] : c[7])
                * ((lane & 16) ? s[8] : c[8]);
    int laneK = __popc(lane & 31);

    float ar[16], ai[16];
#pragma unroll
    for (int l = 0; l < 16; l++) {
        float r = laneF
                * ((l & 1) ? s[0] : c[0])
                * ((l & 2) ? s[2] : c[2])
                * ((l & 4) ? s[4] : c[4])
                * ((l & 8) ? s[6] : c[6]);
        int k = (laneK + __popc(l)) & 3;   // amplitude = r * (-i)^k
        ar[l] = (k == 0) ? r : ((k == 2) ? -r : 0.0f);
        ai[l] = (k == 1) ? -r : ((k == 3) ? r : 0.0f);
    }

    const float4* tcs = g_theta + ch * 8;

    // ---- 8 (CRZ, CRX) gate pairs, in PAIRS order. ----
    gate_laneC_localT<1, 1>(ar, ai, tcs[0], lane);   // (c=q1, t=q0)
    gate_laneC_localT<2, 2>(ar, ai, tcs[1], lane);   // (c=q3, t=q2)
    gate_localC_localT<2, 1>(ar, ai, tcs[2]);        // (c=q2, t=q0)
    gate_q8_q7(ar, ai, tcs[3], lane);                // (c=q8, t=q7)
    gate_laneC_localT<4, 4>(ar, ai, tcs[4], lane);   // (c=q5, t=q4)
    gate_laneC_localT<8, 8>(ar, ai, tcs[5], lane);   // (c=q7, t=q6)
    gate_localC_localT<8, 4>(ar, ai, tcs[6]);        // (c=q6, t=q4)
    gate_localC_localT<4, 1>(ar, ai, tcs[7]);        // (c=q4, t=q0)

    // ---- <Z_0>: +|a|^2 where q0 bit (local bit 0) = 0, else -|a|^2. ----
    float z = 0.0f;
#pragma unroll
    for (int l = 0; l < 16; l++) {
        float p = ar[l] * ar[l] + ai[l] * ai[l];
        z += (l & 1) ? -p : p;
    }
#pragma unroll
    for (int off = 16; off > 0; off >>= 1)
        z += __shfl_xor_sync(0xffffffffu, z, off);

    if (lane == 0) {
        // out layout (B, 30, 30, C), interior at (i+1, j+1).
        out[((b * 30 + i + 1) * 30 + (j + 1)) * 4 + ch] = (z + 1.0f) * 0.5f;
    }
}

// ----------------------------- launch --------------------------------------
extern "C" void kernel_launch(void* const* d_in, const int* in_sizes, int n_in,
                              void* d_out, int out_size) {
    const float* x  = (const float*)d_in[0];   // (8,30,30,3)
    const float* qp = (const float*)d_in[1];   // (4,16)
    float* out = (float*)d_out;                // (8,30,30,4)

    // Zero the padded border (d_out is poisoned).
    cudaMemsetAsync(d_out, 0, (size_t)out_size * sizeof(float));

    precompute_kernel<<<(NPIX + 32 + 255) / 256, 256>>>(x, qp);

    // 25088 warps = 3136 blocks x 8 warps.
    quanv_kernel<<<NSIM / 8, 256>>>(out);
}

// round 2
// speedup vs baseline: 5.4412x; 5.4412x over previous
#include <cuda_runtime.h>
#include <math_constants.h>

// ---------------------------------------------------------------------------
// Quanv 3x3 layer via tree-tensor-network / qubit-channel contraction.
//
// Circuit graph is a tree rooted at qubit 0. Each qubit controls exactly one
// gate, after all gates targeting it, and is never used afterwards. Hence
// each controlled gate (c,t) acts on the target's reduced density matrix as
//      rho_t <- p0 * rho_t + p1 * M rho_t M^dag,   M = RX(tx) RZ(tz),
// with p1 = population of |1> of the control at that point (coherences of the
// control drop out when tracing). Whole 9-qubit sim = eight 2x2 channels.
//
// Parametrization: rho = [[r0, wr+i*wi],[wr-i*wi, 1-r0]].
//   r0'  = lerp(r0, Cx*r0 + (1-Cx)/2 + Sx*(Sz*wr - Cz*wi), p1)
//   wr'  = lerp(wr, Cz*wr + Sz*wi,                          p1)
//   wi'  = lerp(wi, Cx*(Cz*wi - Sz*wr) + Sx*(r0 - 0.5),     p1)
// Encoding RX(2*pi*a - pi) on |0>:
//   r0_init = (1 - cos 2pi a)/2,  wr = 0,  wi = -sin(2pi a)/2
//   control leaf p1 = (1 + cos 2pi a)/2
// Output feature = (<Z0>+1)/2 = final r0 of qubit 0.
// ---------------------------------------------------------------------------

#define NPIX (8 * 30 * 30)        // 7200
#define NSIM (8 * 4 * 28 * 28)    // 25088

__device__ float2 g_pix[NPIX];    // (cos 2*pi*a, sin 2*pi*a) per pixel
__device__ float4 g_g[4 * 8];     // per (channel, gate): Cz, Sz, Cx, Sx

// --------------------------- precompute ------------------------------------
// Also zeroes the output (incl. padded border): out has 8*30*30*4 floats =
// exactly one float4 per pixel thread.
__global__ void precompute_kernel(const float* __restrict__ x,
                                  const float* __restrict__ qp,
                                  float4* __restrict__ out4) {
    int tid = blockIdx.x * blockDim.x + threadIdx.x;
    if (tid < NPIX) {
        out4[tid] = make_float4(0.f, 0.f, 0.f, 0.f);
        const float* px = x + 3 * tid;
        float a = (px[0] + px[1] + px[2]) * (1.0f / 3.0f);
        float sn, cs;
        sincosf(2.0f * CUDART_PI_F * a, &sn, &cs);
        g_pix[tid] = make_float2(cs, sn);
    } else if (tid < NPIX + 32) {
        int e = tid - NPIX;                 // e = ch*8 + k
        int ch = e >> 3, k = e & 7;
        float tz = qp[ch * 16 + 2 * k];
        float tx = qp[ch * 16 + 2 * k + 1];
        float Sz, Cz, Sx, Cx;
        sincosf(tz, &Sz, &Cz);
        sincosf(tx, &Sx, &Cx);
        g_g[e] = make_float4(Cz, Sz, Cx, Sx);
    }
}

// ------------------------- channel helpers ---------------------------------
__device__ __forceinline__ void chan_full(float p1, float4 g,
                                          float& r0, float& wr, float& wi) {
    float Cz = g.x, Sz = g.y, Cx = g.z, Sx = g.w;
    float nr0 = fmaf(Cx, r0, 0.5f * (1.0f - Cx)) + Sx * fmaf(Sz, wr, -Cz * wi);
    float nwr = fmaf(Cz, wr, Sz * wi);
    float nwi = fmaf(Cx, fmaf(Cz, wi, -Sz * wr), Sx * (r0 - 0.5f));
    r0 = fmaf(p1, nr0 - r0, r0);
    wr = fmaf(p1, nwr - wr, wr);
    wi = fmaf(p1, nwi - wi, wi);
}

__device__ __forceinline__ float chan_r0(float p1, float4 g,
                                         float r0, float wr, float wi) {
    float nr0 = fmaf(g.z, r0, 0.5f * (1.0f - g.z)) + g.w * fmaf(g.y, wr, -g.x * wi);
    return fmaf(p1, nr0 - r0, r0);
}

// ----------------------------- main kernel ---------------------------------
__global__ void __launch_bounds__(256) quanv_kernel(float* __restrict__ out) {
    int tid = blockIdx.x * blockDim.x + threadIdx.x;   // one thread = one sim
    if (tid >= NSIM) return;

    int b   = tid / 3136;              // 4*28*28
    int r1  = tid - b * 3136;
    int ch  = r1 / 784;
    int pos = r1 - ch * 784;
    int i   = pos / 28;
    int j   = pos - i * 28;

    // 9 pixel coefficient pairs (cos 2pi a, sin 2pi a).
    float cs[9], sn[9];
    const float2* pix = g_pix + b * 900 + i * 30 + j;
#pragma unroll
    for (int q = 0; q < 9; q++) {
        float2 v = __ldg(&pix[(q / 3) * 30 + (q % 3)]);
        cs[q] = v.x; sn[q] = v.y;
    }

    const float4* G = g_g + ch * 8;
    float4 G0 = G[0], G1 = G[1], G2 = G[2], G3 = G[3];
    float4 G4 = G[4], G5 = G[5], G6 = G[6], G7 = G[7];

    // Leaf-control excited populations: p1 = (1 + cos)/2.
    float p1_1 = 0.5f * (1.0f + cs[1]);
    float p1_3 = 0.5f * (1.0f + cs[3]);
    float p1_5 = 0.5f * (1.0f + cs[5]);
    float p1_8 = 0.5f * (1.0f + cs[8]);

    // Targeted-qubit initial states: r0 = (1-cos)/2, wr = 0, wi = -sin/2.
    float r0_0 = 0.5f * (1.0f - cs[0]), wr0 = 0.0f, wi0 = -0.5f * sn[0];
    float r0_4 = 0.5f * (1.0f - cs[4]), wr4 = 0.0f, wi4 = -0.5f * sn[4];

    // Gate sequence (PAIRS order).
    chan_full(p1_1, G0, r0_0, wr0, wi0);                                   // (1,0)
    float r2 = chan_r0(p1_3, G1, 0.5f * (1.0f - cs[2]), 0.0f, -0.5f * sn[2]); // (3,2)
    chan_full(1.0f - r2, G2, r0_0, wr0, wi0);                              // (2,0)
    float r7 = chan_r0(p1_8, G3, 0.5f * (1.0f - cs[7]), 0.0f, -0.5f * sn[7]); // (8,7)
    chan_full(p1_5, G4, r0_4, wr4, wi4);                                   // (5,4)
    float r6 = chan_r0(1.0f - r7, G5, 0.5f * (1.0f - cs[6]), 0.0f, -0.5f * sn[6]); // (7,6)
    float r4 = chan_r0(1.0f - r6, G6, r0_4, wr4, wi4);                     // (6,4)
    float rf = chan_r0(1.0f - r4, G7, r0_0, wr0, wi0);                     // (4,0)

    // feat = (z+1)/2 = r0 of qubit 0. Layout (B, 30, 30, C), interior.
    out[((b * 30 + i + 1) * 30 + (j + 1)) * 4 + ch] = rf;
}

// ----------------------------- launch --------------------------------------
extern "C" void kernel_launch(void* const* d_in, const int* in_sizes, int n_in,
                              void* d_out, int out_size) {
    const float* x  = (const float*)d_in[0];   // (8,30,30,3)
    const float* qp = (const float*)d_in[1];   // (4,16)
    float* out = (float*)d_out;                // (8,30,30,4)

    precompute_kernel<<<(NPIX + 32 + 255) / 256, 256>>>(x, qp, (float4*)out);
    quanv_kernel<<<NSIM / 256, 256>>>(out);    // 25088 = 98 * 256
}

// round 4
// speedup vs baseline: 6.4428x; 1.1841x over previous
#include <cuda_runtime.h>
#include <math_constants.h>

// ---------------------------------------------------------------------------
// Quanv 3x3 layer, fully fused single kernel.
//
// Math (from R2): the circuit's entangling graph is a tree rooted at qubit 0;
// every qubit controls exactly one gate after all gates targeting it. Each
// controlled gate (c,t) is therefore a qubit channel on t's 2x2 reduced
// density matrix rho = [[r0, wr+i*wi],[wr-i*wi, 1-r0]]:
//   r0' = lerp(r0, Cx*r0 + (1-Cx)/2 + Sx*(Sz*wr - Cz*wi), p1)
//   wr' = lerp(wr, Cz*wr + Sz*wi,                          p1)
//   wi' = lerp(wi, Cx*(Cz*wi - Sz*wr) + Sx*(r0 - 0.5),     p1)
// with p1 = control's |1> population. Encoding RX(2*pi*a - pi) on |0>:
//   r0 = (1 - cos 2pi a)/2, wr = 0, wi = -sin(2pi a)/2 ; leaf p1 = (1+cos)/2.
// Output feature = final r0 of qubit 0.
//
// Tiling: one block per (image b, output row i): 8*28 = 224 blocks, 128 thr.
// Phase 1 (cooperative, smem): 90 pixel trig pairs for the 3x30 strip +
// all 32 gate-constant float4s. Phase 2: 112 threads (4 ch x 28 cols) run the
// 8-channel chain. Blocks with i==0 also zero the 116 border pixels of their
// image (disjoint from every interior write -> race-free).
// ---------------------------------------------------------------------------

__global__ void __launch_bounds__(128) quanv_fused(const float* __restrict__ x,
                                                   const float* __restrict__ qp,
                                                   float* __restrict__ out) {
    __shared__ float2 pixs[90];   // (cos 2pi a, sin 2pi a), rows i..i+2 x 30
    __shared__ float4 gs[32];     // per (channel, gate): Cz, Sz, Cx, Sx

    int blk = blockIdx.x;
    int b = blk / 28;
    int i = blk - b * 28;
    int t = threadIdx.x;

    // ---- Phase 1a: pixel strip trig (threads 0..89). ----
    if (t < 90) {
        int dr = t / 30;
        int c  = t - dr * 30;
        const float* px = x + (((b * 30) + i + dr) * 30 + c) * 3;
        float a = (px[0] + px[1] + px[2]) * (1.0f / 3.0f);
        float sn, cs;
        sincosf(2.0f * CUDART_PI_F * a, &sn, &cs);
        pixs[t] = make_float2(cs, sn);
    } else if (t >= 96) {
        // ---- Phase 1b: gate constants (threads 96..127 -> 32 gates). ----
        int e = t - 96;                   // e = ch*8 + k
        int ch = e >> 3, k = e & 7;
        float tz = qp[ch * 16 + 2 * k];
        float tx = qp[ch * 16 + 2 * k + 1];
        float Sz, Cz, Sx, Cx;
        sincosf(tz, &Sz, &Cz);
        sincosf(tx, &Sx, &Cx);
        gs[e] = make_float4(Cz, Sz, Cx, Sx);
    }

    // ---- Border zeroing (only i==0 blocks; 116 border pixels per image). ----
    if (i == 0 && t < 116) {
        int r, c;
        if      (t < 30) { r = 0;          c = t;      }
        else if (t < 60) { r = 29;         c = t - 30; }
        else if (t < 88) { r = t - 60 + 1; c = 0;      }
        else             { r = t - 88 + 1; c = 29;     }
        ((float4*)out)[b * 900 + r * 30 + c] = make_float4(0.f, 0.f, 0.f, 0.f);
    }

    __syncthreads();

    // ---- Phase 2: one thread per (channel, column). ----
    if (t >= 112) return;
    int ch = t / 28;
    int j  = t - ch * 28;

    float cs[9], sn[9];
#pragma unroll
    for (int q = 0; q < 9; q++) {
        float2 v = pixs[(q / 3) * 30 + j + (q % 3)];
        cs[q] = v.x; sn[q] = v.y;
    }

    float4 G0 = gs[ch * 8 + 0], G1 = gs[ch * 8 + 1];
    float4 G2 = gs[ch * 8 + 2], G3 = gs[ch * 8 + 3];
    float4 G4 = gs[ch * 8 + 4], G5 = gs[ch * 8 + 5];
    float4 G6 = gs[ch * 8 + 6], G7 = gs[ch * 8 + 7];

    // Leaf-control populations and targeted-qubit initial states.
    float p1_1 = 0.5f * (1.0f + cs[1]);
    float p1_3 = 0.5f * (1.0f + cs[3]);
    float p1_5 = 0.5f * (1.0f + cs[5]);
    float p1_8 = 0.5f * (1.0f + cs[8]);

    float r0_0 = 0.5f * (1.0f - cs[0]), wr0 = 0.0f, wi0 = -0.5f * sn[0];
    float r0_4 = 0.5f * (1.0f - cs[4]), wr4 = 0.0f, wi4 = -0.5f * sn[4];

    // Channel application (full rho update).
    auto chan_full = [](float p1, float4 g, float& r0, float& wr, float& wi) {
        float nr0 = fmaf(g.z, r0, 0.5f * (1.0f - g.z)) + g.w * fmaf(g.y, wr, -g.x * wi);
        float nwr = fmaf(g.x, wr, g.y * wi);
        float nwi = fmaf(g.z, fmaf(g.x, wi, -g.y * wr), g.w * (r0 - 0.5f));
        r0 = fmaf(p1, nr0 - r0, r0);
        wr = fmaf(p1, nwr - wr, wr);
        wi = fmaf(p1, nwi - wi, wi);
    };
    // Channel application, only r0 needed afterwards.
    auto chan_r0 = [](float p1, float4 g, float r0, float wr, float wi) {
        float nr0 = fmaf(g.z, r0, 0.5f * (1.0f - g.z)) + g.w * fmaf(g.y, wr, -g.x * wi);
        return fmaf(p1, nr0 - r0, r0);
    };

    // Gate sequence (PAIRS order).
    chan_full(p1_1, G0, r0_0, wr0, wi0);                                        // (1,0)
    float r2 = chan_r0(p1_3, G1, 0.5f * (1.0f - cs[2]), 0.0f, -0.5f * sn[2]);   // (3,2)
    chan_full(1.0f - r2, G2, r0_0, wr0, wi0);                                   // (2,0)
    float r7 = chan_r0(p1_8, G3, 0.5f * (1.0f - cs[7]), 0.0f, -0.5f * sn[7]);   // (8,7)
    chan_full(p1_5, G4, r0_4, wr4, wi4);                                        // (5,4)
    float r6 = chan_r0(1.0f - r7, G5, 0.5f * (1.0f - cs[6]), 0.0f, -0.5f * sn[6]); // (7,6)
    float r4 = chan_r0(1.0f - r6, G6, r0_4, wr4, wi4);                          // (6,4)
    float rf = chan_r0(1.0f - r4, G7, r0_0, wr0, wi0);                          // (4,0)

    // Output (B, 30, 30, C), interior at (i+1, j+1).
    out[(((b * 30) + i + 1) * 30 + (j + 1)) * 4 + ch] = rf;
}

// ----------------------------- launch --------------------------------------
extern "C" void kernel_launch(void* const* d_in, const int* in_sizes, int n_in,
                              void* d_out, int out_size) {
    const float* x  = (const float*)d_in[0];   // (8,30,30,3)
    const float* qp = (const float*)d_in[1];   // (4,16)
    float* out = (float*)d_out;                // (8,30,30,4)

    quanv_fused<<<8 * 28, 128>>>(x, qp, out);  // 224 blocks, one graph node
}

// round 5
// speedup vs baseline: 6.5075x; 1.0101x over previous
#include <cuda_runtime.h>
#include <math_constants.h>

// ---------------------------------------------------------------------------
// Quanv 3x3 layer, fully fused single kernel (single-wave tiling).
//
// Math: the circuit's entangling graph is a tree rooted at qubit 0; every
// qubit controls exactly one gate after all gates targeting it. Each
// controlled gate (c,t) is a qubit channel on t's 2x2 reduced density matrix
// rho = [[r0, wr+i*wi],[wr-i*wi, 1-r0]]:
//   r0' = lerp(r0, Cx*r0 + (1-Cx)/2 + Sx*(Sz*wr - Cz*wi), p1)
//   wr' = lerp(wr, Cz*wr + Sz*wi,                          p1)
//   wi' = lerp(wi, Cx*(Cz*wi - Sz*wr) + Sx*(r0 - 0.5),     p1)
// with p1 = control's |1> population. Encoding RX(2*pi*a - pi) on |0>:
//   r0 = (1 - cos 2pi a)/2, wr = 0, wi = -sin(2pi a)/2 ; leaf p1 = (1+cos)/2.
// Output feature = final r0 of qubit 0.
//
// Tiling: one block per (image b, row-pair ih): 8*14 = 112 blocks (< 148 SMs
// -> ONE wave), 256 threads. Phase 1 (smem): 120 pixel trig pairs for the
// 4x30 input strip + 32 gate-constant float4s (MUFU __sinf/__cosf — args
// bounded by 2*pi, approx error ~1e-6 << 1e-3 gate). Phase 2: 224 threads
// (2 rows x 4 ch x 28 cols) run the 8-channel chain. ih==0 blocks also zero
// the 116 border pixels of their image (disjoint addresses -> race-free).
// ---------------------------------------------------------------------------

__global__ void __launch_bounds__(256) quanv_fused(const float* __restrict__ x,
                                                   const float* __restrict__ qp,
                                                   float* __restrict__ out) {
    __shared__ float2 pixs[120];  // (cos 2pi a, sin 2pi a), rows i0..i0+3 x 30
    __shared__ float4 gs[32];     // per (channel, gate): Cz, Sz, Cx, Sx

    int blk = blockIdx.x;
    int b  = blk / 14;
    int ih = blk - b * 14;
    int i0 = ih * 2;              // first of the two output rows
    int t  = threadIdx.x;

    // ---- Phase 1a: pixel strip trig (threads 0..119). ----
    if (t < 120) {
        int dr = t / 30;
        int c  = t - dr * 30;
        const float* px = x + (((b * 30) + i0 + dr) * 30 + c) * 3;
        float a = (px[0] + px[1] + px[2]) * (1.0f / 3.0f);
        float ang = 2.0f * CUDART_PI_F * a;
        pixs[t] = make_float2(__cosf(ang), __sinf(ang));
    } else if (t < 152) {
        // ---- Phase 1b: gate constants (threads 120..151 -> 32 gates). ----
        int e = t - 120;                  // e = ch*8 + k
        int ch = e >> 3, k = e & 7;
        float tz = qp[ch * 16 + 2 * k];
        float tx = qp[ch * 16 + 2 * k + 1];
        gs[e] = make_float4(__cosf(tz), __sinf(tz), __cosf(tx), __sinf(tx));
    }

    // ---- Border zeroing (ih==0 blocks; threads 140..255 -> 116 px). ----
    if (ih == 0 && t >= 140) {
        int e = t - 140;
        int r, c;
        if      (e < 30) { r = 0;          c = e;      }
        else if (e < 60) { r = 29;         c = e - 30; }
        else if (e < 88) { r = e - 60 + 1; c = 0;      }
        else             { r = e - 88 + 1; c = 29;     }
        ((float4*)out)[b * 900 + r * 30 + c] = make_float4(0.f, 0.f, 0.f, 0.f);
    }

    __syncthreads();

    // ---- Phase 2: one thread per (row, channel, column). ----
    if (t >= 224) return;
    int rw  = t / 112;            // 0 or 1 -> output row i0+rw
    int rem = t - rw * 112;
    int ch  = rem / 28;
    int j   = rem - ch * 28;

    float cs[9], sn[9];
#pragma unroll
    for (int q = 0; q < 9; q++) {
        float2 v = pixs[(rw + q / 3) * 30 + j + (q % 3)];
        cs[q] = v.x; sn[q] = v.y;
    }

    float4 G0 = gs[ch * 8 + 0], G1 = gs[ch * 8 + 1];
    float4 G2 = gs[ch * 8 + 2], G3 = gs[ch * 8 + 3];
    float4 G4 = gs[ch * 8 + 4], G5 = gs[ch * 8 + 5];
    float4 G6 = gs[ch * 8 + 6], G7 = gs[ch * 8 + 7];

    // Leaf-control populations and targeted-qubit initial states.
    float p1_1 = 0.5f * (1.0f + cs[1]);
    float p1_3 = 0.5f * (1.0f + cs[3]);
    float p1_5 = 0.5f * (1.0f + cs[5]);
    float p1_8 = 0.5f * (1.0f + cs[8]);

    float r0_0 = 0.5f * (1.0f - cs[0]), wr0 = 0.0f, wi0 = -0.5f * sn[0];
    float r0_4 = 0.5f * (1.0f - cs[4]), wr4 = 0.0f, wi4 = -0.5f * sn[4];

    auto chan_full = [](float p1, float4 g, float& r0, float& wr, float& wi) {
        float nr0 = fmaf(g.z, r0, 0.5f * (1.0f - g.z)) + g.w * fmaf(g.y, wr, -g.x * wi);
        float nwr = fmaf(g.x, wr, g.y * wi);
        float nwi = fmaf(g.z, fmaf(g.x, wi, -g.y * wr), g.w * (r0 - 0.5f));
        r0 = fmaf(p1, nr0 - r0, r0);
        wr = fmaf(p1, nwr - wr, wr);
        wi = fmaf(p1, nwi - wi, wi);
    };
    auto chan_r0 = [](float p1, float4 g, float r0, float wr, float wi) {
        float nr0 = fmaf(g.z, r0, 0.5f * (1.0f - g.z)) + g.w * fmaf(g.y, wr, -g.x * wi);
        return fmaf(p1, nr0 - r0, r0);
    };

    // Gate sequence (PAIRS order).
    chan_full(p1_1, G0, r0_0, wr0, wi0);                                        // (1,0)
    float r2 = chan_r0(p1_3, G1, 0.5f * (1.0f - cs[2]), 0.0f, -0.5f * sn[2]);   // (3,2)
    chan_full(1.0f - r2, G2, r0_0, wr0, wi0);                                   // (2,0)
    float r7 = chan_r0(p1_8, G3, 0.5f * (1.0f - cs[7]), 0.0f, -0.5f * sn[7]);   // (8,7)
    chan_full(p1_5, G4, r0_4, wr4, wi4);                                        // (5,4)
    float r6 = chan_r0(1.0f - r7, G5, 0.5f * (1.0f - cs[6]), 0.0f, -0.5f * sn[6]); // (7,6)
    float r4 = chan_r0(1.0f - r6, G6, r0_4, wr4, wi4);                          // (6,4)
    float rf = chan_r0(1.0f - r4, G7, r0_0, wr0, wi0);                          // (4,0)

    // Output (B, 30, 30, C), interior at (i0+rw+1, j+1).
    out[(((b * 30) + i0 + rw + 1) * 30 + (j + 1)) * 4 + ch] = rf;
}

// ----------------------------- launch --------------------------------------
extern "C" void kernel_launch(void* const* d_in, const int* in_sizes, int n_in,
                              void* d_out, int out_size) {
    const float* x  = (const float*)d_in[0];   // (8,30,30,3)
    const float* qp = (const float*)d_in[1];   // (4,16)
    float* out = (float*)d_out;                // (8,30,30,4)

    quanv_fused<<<112, 256>>>(x, qp, out);     // single wave, one graph node
}